// round 13
// baseline (speedup 1.0000x reference)
#include <cuda_runtime.h>
#include <cuda_bf16.h>
#include <stdint.h>

#define D_MODEL 1024
#define NHEADS  16
#define HD      64
#define BATCH   4
#define SEQ     2048
#define BH      64
#define MTOK    8192
#define QSCALE  0.18033688011112042f   // 0.125 * log2(e)
#define LOG2E   1.4426950408889634f
// S_log2 = (hh*16384 + cr*128) * QSCALE / 2048^2 = hh*QSCALE/256 + cr*QSCALE/32768
#define SC1 (0.18033688011112042f / 256.0f)
#define SC2 (0.18033688011112042f / 32768.0f)

// ---------------- scratch globals (allocation-free) ----------------
__device__ char g_q1[8388608], g_q0[8388608];           // Q int8 limbs [bh][s][d]
__device__ char g_k1[8388608], g_k0[8388608];           // K int8 limbs
__device__ __nv_bfloat16 g_vh[8388608], g_vl[8388608];  // V bf16 hi/lo
__device__ __nv_bfloat16 g_xh[8388608], g_xl[8388608];
__device__ __nv_bfloat16 g_wh[4194304], g_wl[4194304];
__device__ __nv_bfloat16 g_ch[8388608], g_cl[8388608];

// ---------------- helpers ----------------
__device__ __forceinline__ uint32_t su32(const void* p) {
    uint32_t a;
    asm("{ .reg .u64 t; cvta.to.shared.u64 t, %1; cvt.u32.u64 %0, t; }" : "=r"(a) : "l"(p));
    return a;
}
__device__ __forceinline__ void cpa16(uint32_t dst, const void* src) {
    asm volatile("cp.async.cg.shared.global [%0], [%1], 16;" :: "r"(dst), "l"(src));
}
__device__ __forceinline__ void cpa4(uint32_t dst, const void* src) {
    asm volatile("cp.async.ca.shared.global [%0], [%1], 4;" :: "r"(dst), "l"(src));
}
#define CP_COMMIT() asm volatile("cp.async.commit_group;" ::: "memory")
#define CP_WAIT0()  asm volatile("cp.async.wait_group 0;" ::: "memory")
#define CP_WAIT1()  asm volatile("cp.async.wait_group 1;" ::: "memory")

__device__ __forceinline__ void ldsm4(uint32_t* r, uint32_t addr) {
    asm volatile("ldmatrix.sync.aligned.m8n8.x4.shared.b16 {%0,%1,%2,%3}, [%4];"
                 : "=r"(r[0]), "=r"(r[1]), "=r"(r[2]), "=r"(r[3]) : "r"(addr));
}
__device__ __forceinline__ void ldsm4t(uint32_t* r, uint32_t addr) {
    asm volatile("ldmatrix.sync.aligned.m8n8.x4.trans.shared.b16 {%0,%1,%2,%3}, [%4];"
                 : "=r"(r[0]), "=r"(r[1]), "=r"(r[2]), "=r"(r[3]) : "r"(addr));
}
__device__ __forceinline__ void mma_bf16(float* c, const uint32_t* a, const uint32_t* b) {
    asm volatile("mma.sync.aligned.m16n8k16.row.col.f32.bf16.bf16.f32 "
                 "{%0,%1,%2,%3}, {%4,%5,%6,%7}, {%8,%9}, {%0,%1,%2,%3};"
                 : "+f"(c[0]), "+f"(c[1]), "+f"(c[2]), "+f"(c[3])
                 : "r"(a[0]), "r"(a[1]), "r"(a[2]), "r"(a[3]), "r"(b[0]), "r"(b[1]));
}
__device__ __forceinline__ void mma_s8(int* c, const uint32_t* a, const uint32_t* b) {
    asm volatile("mma.sync.aligned.m16n8k32.row.col.s32.s8.s8.s32 "
                 "{%0,%1,%2,%3}, {%4,%5,%6,%7}, {%8,%9}, {%0,%1,%2,%3};"
                 : "+r"(c[0]), "+r"(c[1]), "+r"(c[2]), "+r"(c[3])
                 : "r"(a[0]), "r"(a[1]), "r"(a[2]), "r"(a[3]), "r"(b[0]), "r"(b[1]));
}
__device__ __forceinline__ float ex2f(float x) {
    float r; asm("ex2.approx.f32 %0, %1;" : "=f"(r) : "f"(x)); return r;
}
// split pair (v0,v1) -> packed bf16 hi pair + bf16 lo-residual pair
__device__ __forceinline__ void split2(float v0, float v1, uint32_t& hi, uint32_t& lo) {
    uint32_t b0 = __float_as_uint(v0), b1 = __float_as_uint(v1);
    uint32_t h0 = (b0 + 0x7FFFu + ((b0 >> 16) & 1u)) & 0xFFFF0000u;
    uint32_t h1 = (b1 + 0x7FFFu + ((b1 >> 16) & 1u)) & 0xFFFF0000u;
    hi = (h0 >> 16) | h1;
    float l0 = v0 - __uint_as_float(h0);
    float l1 = v1 - __uint_as_float(h1);
    asm("cvt.rn.bf16x2.f32 %0, %1, %2;" : "=r"(lo) : "f"(l1), "f"(l0));
}
// quantize v to 15-bit fixed point (scale 2048), emit s8 limbs
__device__ __forceinline__ void quant15(float v, int& hi, int& lo) {
    int i = __float2int_rn(fminf(fmaxf(v * 2048.0f, -16000.0f), 16000.0f));
    hi = (i + 64) >> 7;
    lo = i - (hi << 7);
}

// ---------------- prep: fp32 -> bf16 hi/lo ----------------
__global__ void split_x_kernel(const float* __restrict__ src) {
    for (size_t i = (size_t)blockIdx.x * blockDim.x + threadIdx.x; i < (size_t)MTOK * D_MODEL;
         i += (size_t)gridDim.x * blockDim.x) {
        float v = src[i];
        __nv_bfloat16 h = __float2bfloat16(v);
        g_xh[i] = h;
        g_xl[i] = __float2bfloat16(v - __bfloat162float(h));
    }
}
__global__ void split_w_kernel(const float* __restrict__ w0, const float* __restrict__ w1,
                               const float* __restrict__ w2, const float* __restrict__ w3) {
    int idx = blockIdx.y;
    const float* src = (idx == 0) ? w0 : (idx == 1) ? w1 : (idx == 2) ? w2 : w3;
    size_t off = (size_t)idx * 1048576;
    for (size_t i = (size_t)blockIdx.x * blockDim.x + threadIdx.x; i < 1048576;
         i += (size_t)gridDim.x * blockDim.x) {
        float v = src[i];
        __nv_bfloat16 h = __float2bfloat16(v);
        g_wh[off + i] = h;
        g_wl[off + i] = __float2bfloat16(v - __bfloat162float(h));
    }
}

// ---------------- projection GEMM: 128m x 128n, split bf16, mma.sync ----------
// OPROJ=0: QKV via blockIdx.z (0:Q int8 limbs, 1:K int8 limbs, 2:V bf16 hi/lo)
// OPROJ=1: O projection (g_c @ Wo^T + bias) -> fp32 out
#define PST 40960

template<int OPROJ>
__global__ void __launch_bounds__(256, 2)
proj_kernel(const float* __restrict__ bias, float* __restrict__ out)
{
    extern __shared__ char smem[];
    const uint32_t sb = su32(smem);
    const int tid = threadIdx.x;
    const int lane = tid & 31, wid = tid >> 5;
    const int wm = wid >> 2, wn = wid & 3;
    const int g = lane >> 2, tig = lane & 3;
    const int m0 = blockIdx.x * 128, n0 = blockIdx.y * 128;
    const int mode = OPROJ ? 3 : (int)blockIdx.z;

    const __nv_bfloat16* Ah = OPROJ ? g_ch : g_xh;
    const __nv_bfloat16* Al = OPROJ ? g_cl : g_xl;
    const __nv_bfloat16* Bh = g_wh + (size_t)mode * 1048576;
    const __nv_bfloat16* Bl = g_wl + (size_t)mode * 1048576;

    float acc[4][4][4];
#pragma unroll
    for (int i = 0; i < 4; i++)
#pragma unroll
        for (int j = 0; j < 4; j++)
#pragma unroll
            for (int e = 0; e < 4; e++) acc[i][j][e] = 0.0f;

    auto load_stage = [&](int kt, int buf) {
        uint32_t base = sb + buf * PST;
#pragma unroll
        for (int t = 0; t < 8; t++) {
            int vi = tid + t * 256;
            int tile = vi >> 9;
            int row = (vi >> 2) & 127;
            int ch = vi & 3;
            const __nv_bfloat16* src;
            if      (tile == 0) src = Ah + (size_t)(m0 + row) * 1024 + kt + ch * 8;
            else if (tile == 1) src = Al + (size_t)(m0 + row) * 1024 + kt + ch * 8;
            else if (tile == 2) src = Bh + (size_t)(n0 + row) * 1024 + kt + ch * 8;
            else                src = Bl + (size_t)(n0 + row) * 1024 + kt + ch * 8;
            cpa16(base + tile * 10240 + row * 80 + ch * 16, src);
        }
        CP_COMMIT();
    };

    load_stage(0, 0);
    for (int s = 0; s < 32; s++) {
        if (s < 31) { load_stage((s + 1) * 32, (s + 1) & 1); CP_WAIT1(); }
        else CP_WAIT0();
        __syncthreads();
        uint32_t base = sb + (s & 1) * PST;
#pragma unroll
        for (int ks = 0; ks < 2; ks++) {
            uint32_t afh[4][4], afl[4][4];
#pragma unroll
            for (int mf = 0; mf < 4; mf++) {
                uint32_t a = base + (uint32_t)(wm * 64 + mf * 16 + (lane & 15)) * 80
                           + (ks * 16 + (lane >> 4) * 8) * 2;
                ldsm4(afh[mf], a);
                ldsm4(afl[mf], a + 10240);
            }
#pragma unroll
            for (int g2 = 0; g2 < 2; g2++) {
                uint32_t bfh[4], bfl[4];
                uint32_t a = base + 20480
                           + (uint32_t)(wn * 32 + g2 * 16 + (lane & 7) + ((lane >> 4) << 3)) * 80
                           + (ks * 16 + ((lane >> 3) & 1) * 8) * 2;
                ldsm4(bfh, a);
                ldsm4(bfl, a + 10240);
#pragma unroll
                for (int mf = 0; mf < 4; mf++)
#pragma unroll
                    for (int j = 0; j < 2; j++) {
                        float* c = acc[mf][g2 * 2 + j];
                        mma_bf16(c, afh[mf], &bfh[j * 2]);
                        mma_bf16(c, afh[mf], &bfl[j * 2]);
                        mma_bf16(c, afl[mf], &bfh[j * 2]);
                    }
            }
        }
        __syncthreads();
    }

    // epilogue
    char* Hq = (mode == 0) ? g_q1 : g_k1;
    char* Lq = (mode == 0) ? g_q0 : g_k0;
#pragma unroll
    for (int mf = 0; mf < 4; mf++) {
#pragma unroll
        for (int half = 0; half < 2; half++) {
            int m = m0 + wm * 64 + mf * 16 + g + half * 8;
#pragma unroll
            for (int nf = 0; nf < 4; nf++) {
                int n = n0 + wn * 32 + nf * 8 + 2 * tig;
                float v0 = acc[mf][nf][half * 2];
                float v1 = acc[mf][nf][half * 2 + 1];
                if (OPROJ) {
                    float2 o = make_float2(v0 + bias[n], v1 + bias[n + 1]);
                    *(float2*)(out + (size_t)m * 1024 + n) = o;
                } else {
                    int b = m >> 11, ss = m & 2047;
                    int h = n >> 6, d = n & 63;
                    size_t addr = (((size_t)(b * 16 + h) * 2048) + ss) * 64 + d;
                    if (mode == 2) {
                        uint32_t hi, lo;
                        split2(v0, v1, hi, lo);
                        *(uint32_t*)(g_vh + addr) = hi;
                        *(uint32_t*)(g_vl + addr) = lo;
                    } else {
                        int h0, l0, h1, l1;
                        quant15(v0, h0, l0);
                        quant15(v1, h1, l1);
                        *(uint16_t*)(Hq + addr) = (uint16_t)((h0 & 0xFF) | ((h1 & 0xFF) << 8));
                        *(uint16_t*)(Lq + addr) = (uint16_t)((l0 & 0xFF) | ((l1 & 0xFF) << 8));
                    }
                }
            }
        }
    }
}

// ---------------- attention: int8 S (IMMA k32) + bf16 PV, double-buffered -------
// 8 warps x 16 q-rows, 256 thr, 1 CTA/SM.
// Q limbs: 128 x 64B rows, stride 80B, 10240B each.
// KV stage: K1(10240) K0(10240) VH(18432) VL(18432) = 57344B.
#define AI_Q1  0
#define AI_Q0  10240
#define AI_KV  20480
#define AI_KVS 57344
#define AI_SB  (20480 + 2 * 57344)      // 135168
#define AI_SMEM (AI_SB + 2048)          // 137216

__global__ void __launch_bounds__(256, 1)
attn_kernel(const float* __restrict__ bias_table)
{
    extern __shared__ char smem[];
    const uint32_t sb = su32(smem);
    const int tid = threadIdx.x;
    const int lane = tid & 31, w = tid >> 5;
    const int g = lane >> 2, tig = lane & 3;
    const int bh = blockIdx.y;
    const int b = bh >> 4, h = bh & 15;
    const int q0 = blockIdx.x * 128;

    // Q limbs: 1024 x 16B chunks
#pragma unroll
    for (int t2 = 0; t2 < 4; t2++) {
        int vi = tid + t2 * 256;
        int limb = vi >> 9;
        int row = (vi >> 2) & 127;
        int ch = vi & 3;
        const char* src = (limb ? g_q0 : g_q1) + ((size_t)bh * 2048 + q0 + row) * 64 + ch * 16;
        cpa16(sb + (limb ? AI_Q0 : AI_Q1) + row * 80 + ch * 16, src);
    }

    auto issue_kv = [&](int buf, int k0) {
        uint32_t base = sb + AI_KV + buf * AI_KVS;
#pragma unroll
        for (int u = 0; u < 12; u++) {
            int vi = tid + u * 256;
            if (vi < 1024) {               // K limbs
                int limb = vi >> 9;
                int row = (vi >> 2) & 127;
                int ch = vi & 3;
                const char* src = (limb ? g_k0 : g_k1)
                    + ((size_t)bh * 2048 + k0 + row) * 64 + ch * 16;
                cpa16(base + limb * 10240 + row * 80 + ch * 16, src);
            } else {                        // V bf16 hi/lo
                int vj = vi - 1024;
                int tile = vj >> 10;
                int row = (vj >> 3) & 127;
                int ch = vj & 7;
                const __nv_bfloat16* src = (tile ? g_vl : g_vh)
                    + ((size_t)bh * 2048 + k0 + row) * 64 + ch * 8;
                cpa16(base + 20480 + tile * 18432 + row * 144 + ch * 16, src);
            }
        }
        if (tid < 255)
            cpa4(sb + AI_SB + buf * 1024 + tid * 4,
                 bias_table + (size_t)(q0 - k0 + 1920 + tid) * 16 + h);
    };

    issue_kv(0, 0);
    CP_COMMIT();   // group: Q + KV0

    float oacc[8][4];
#pragma unroll
    for (int i = 0; i < 8; i++)
#pragma unroll
        for (int e = 0; e < 4; e++) oacc[i][e] = 0.0f;
    float lsumA = 0.0f, lsumB = 0.0f;

    const int d0 = w * 16 + g - 2 * tig + 127;

    for (int t = 0; t < 16; t++) {
        if (t < 15) { issue_kv((t + 1) & 1, (t + 1) * 128); CP_COMMIT(); CP_WAIT1(); }
        else CP_WAIT0();
        __syncthreads();

        const uint32_t kvb = sb + AI_KV + (t & 1) * AI_KVS;
        const float* sbias = (const float*)(smem + AI_SB + (t & 1) * 1024);

        uint32_t pfh[2][4][4], pfl[2][4][4];

        // ---- S halves: int8 IMMA (hh + cross), then softmax per half ----
#pragma unroll
        for (int hf = 0; hf < 2; hf++) {
            int hh[8][4], cr[8][4];
#pragma unroll
            for (int i = 0; i < 8; i++)
#pragma unroll
                for (int e = 0; e < 4; e++) { hh[i][e] = 0; cr[i][e] = 0; }
#pragma unroll
            for (int ks = 0; ks < 2; ks++) {
                uint32_t q1f[4], q0f[4];
                {
                    uint32_t a = sb + AI_Q1 + (uint32_t)(w * 16 + (lane & 15)) * 80
                               + ks * 32 + (lane >> 4) * 16;
                    ldsm4(q1f, a);
                    ldsm4(q0f, a + 10240);
                }
                uint32_t k1f[4][4], k0f[4][4];
#pragma unroll
                for (int g2 = 0; g2 < 4; g2++) {
                    uint32_t a = kvb
                        + (uint32_t)(hf * 64 + g2 * 16 + (lane & 7) + ((lane >> 4) << 3)) * 80
                        + ks * 32 + ((lane >> 3) & 1) * 16;
                    ldsm4(k1f[g2], a);
                    ldsm4(k0f[g2], a + 10240);
                }
#pragma unroll
                for (int nf2 = 0; nf2 < 8; nf2++) {
                    const uint32_t* b1 = &k1f[nf2 >> 1][(nf2 & 1) * 2];
                    const uint32_t* b0 = &k0f[nf2 >> 1][(nf2 & 1) * 2];
                    mma_s8(hh[nf2], q1f, b1);
                    mma_s8(cr[nf2], q1f, b0);
                    mma_s8(cr[nf2], q0f, b1);
                }
            }
            // softmax: p = 2^(hh*SC1 + cr*SC2 + bias*log2e)
#pragma unroll
            for (int ks2 = 0; ks2 < 4; ks2++) {
#pragma unroll
                for (int j = 0; j < 2; j++) {
                    int nf2 = 2 * ks2 + j;
                    int idx = d0 - (hf * 8 + nf2) * 8;
                    float p0 = ex2f(fmaf((float)hh[nf2][0], SC1,
                               fmaf((float)cr[nf2][0], SC2, sbias[idx] * LOG2E)));
                    float p1 = ex2f(fmaf((float)hh[nf2][1], SC1,
                               fmaf((float)cr[nf2][1], SC2, sbias[idx - 1] * LOG2E)));
                    float p2 = ex2f(fmaf((float)hh[nf2][2], SC1,
                               fmaf((float)cr[nf2][2], SC2, sbias[idx + 8] * LOG2E)));
                    float p3 = ex2f(fmaf((float)hh[nf2][3], SC1,
                               fmaf((float)cr[nf2][3], SC2, sbias[idx + 7] * LOG2E)));
                    lsumA += p0 + p1;
                    lsumB += p2 + p3;
                    split2(p0, p1, pfh[hf][ks2][j * 2 + 0], pfl[hf][ks2][j * 2 + 0]);
                    split2(p2, p3, pfh[hf][ks2][j * 2 + 1], pfl[hf][ks2][j * 2 + 1]);
                }
            }
        }

        // ---- O += P @ V (bf16, both halves) ----
        const uint32_t vb = kvb + 20480;
#pragma unroll
        for (int hf = 0; hf < 2; hf++) {
#pragma unroll
            for (int ks2 = 0; ks2 < 4; ks2++) {
                uint32_t vfh[4][4], vfl[4][4];
#pragma unroll
                for (int dblk = 0; dblk < 4; dblk++) {
                    uint32_t a = vb
                        + (uint32_t)(hf * 64 + ks2 * 16 + (lane & 7) + ((lane >> 3) & 1) * 8) * 144
                        + (dblk * 16 + ((lane >> 4) << 3)) * 2;
                    ldsm4t(vfh[dblk], a);
                    ldsm4t(vfl[dblk], a + 18432);
                }
#pragma unroll
                for (int dblk = 0; dblk < 4; dblk++)
#pragma unroll
                    for (int sub = 0; sub < 2; sub++) {
                        float* o = oacc[dblk * 2 + sub];
                        mma_bf16(o, pfh[hf][ks2], &vfh[dblk][sub * 2]);
                        mma_bf16(o, pfh[hf][ks2], &vfl[dblk][sub * 2]);
                        mma_bf16(o, pfl[hf][ks2], &vfh[dblk][sub * 2]);
                    }
            }
        }
        __syncthreads();
    }

    // ---- row-sum reduce within quad, epilogue ----
    lsumA += __shfl_xor_sync(0xffffffffu, lsumA, 1);
    lsumA += __shfl_xor_sync(0xffffffffu, lsumA, 2);
    lsumB += __shfl_xor_sync(0xffffffffu, lsumB, 1);
    lsumB += __shfl_xor_sync(0xffffffffu, lsumB, 2);
    const float inv0 = 1.0f / lsumA;
    const float inv1 = 1.0f / lsumB;
    const int row0 = q0 + w * 16 + g;
    const size_t base0 = (size_t)(b * 2048 + row0) * 1024 + h * 64;
    const size_t base1 = (size_t)(b * 2048 + row0 + 8) * 1024 + h * 64;
#pragma unroll
    for (int nfd = 0; nfd < 8; nfd++) {
        int d = nfd * 8 + 2 * tig;
        uint32_t hi, lo;
        split2(oacc[nfd][0] * inv0, oacc[nfd][1] * inv0, hi, lo);
        *(uint32_t*)(g_ch + base0 + d) = hi;
        *(uint32_t*)(g_cl + base0 + d) = lo;
        split2(oacc[nfd][2] * inv1, oacc[nfd][3] * inv1, hi, lo);
        *(uint32_t*)(g_ch + base1 + d) = hi;
        *(uint32_t*)(g_cl + base1 + d) = lo;
    }
}

// ---------------- launch ----------------
extern "C" void kernel_launch(void* const* d_in, const int* in_sizes, int n_in,
                              void* d_out, int out_size)
{
    const float* x  = (const float*)d_in[0];
    const float* Wq = (const float*)d_in[1];
    const float* Wk = (const float*)d_in[2];
    const float* Wv = (const float*)d_in[3];
    const float* Wo = (const float*)d_in[4];
    const float* bo = (const float*)d_in[5];
    const float* bt = (const float*)d_in[6];
    float* out = (float*)d_out;

    cudaFuncSetAttribute(proj_kernel<0>, cudaFuncAttributeMaxDynamicSharedMemorySize, 2 * PST);
    cudaFuncSetAttribute(proj_kernel<1>, cudaFuncAttributeMaxDynamicSharedMemorySize, 2 * PST);
    cudaFuncSetAttribute(attn_kernel,    cudaFuncAttributeMaxDynamicSharedMemorySize, AI_SMEM);

    split_x_kernel<<<2048, 256>>>(x);
    split_w_kernel<<<dim3(256, 4), 256>>>(Wq, Wk, Wv, Wo);

    proj_kernel<0><<<dim3(64, 8, 3), 256, 2 * PST>>>(nullptr, nullptr);

    attn_kernel<<<dim3(16, 64), 256, AI_SMEM>>>(bt);

    proj_kernel<1><<<dim3(64, 8), 256, 2 * PST>>>(bo, out);
}

// round 14
// speedup vs baseline: 2.1395x; 2.1395x over previous
#include <cuda_runtime.h>
#include <cuda_fp16.h>
#include <stdint.h>

#define D_MODEL 1024
#define NHEADS  16
#define HD      64
#define BATCH   4
#define SEQ     2048
#define BH      64
#define MTOK    8192
#define QSCALE  0.18033688011112042f   // 0.125 * log2(e)
#define LOG2E   1.4426950408889634f

// ---------------- scratch globals (allocation-free) ----------------
__device__ __half g_qh[8388608], g_ql[8388608];   // Q fp16 hi/lo [bh][s][d]
__device__ __half g_k[8388608];                   // K single fp16
__device__ __half g_v[8388608];                   // V single fp16
__device__ __half g_xh[8388608], g_xl[8388608];   // x fp16 hi/lo
__device__ __half g_w[4194304];                   // 4 x W single fp16
__device__ __half g_ch[8388608], g_cl[8388608];   // ctx fp16 hi/lo

// ---------------- helpers ----------------
__device__ __forceinline__ uint32_t su32(const void* p) {
    uint32_t a;
    asm("{ .reg .u64 t; cvta.to.shared.u64 t, %1; cvt.u32.u64 %0, t; }" : "=r"(a) : "l"(p));
    return a;
}
__device__ __forceinline__ void cpa16(uint32_t dst, const void* src) {
    asm volatile("cp.async.cg.shared.global [%0], [%1], 16;" :: "r"(dst), "l"(src));
}
__device__ __forceinline__ void cpa4(uint32_t dst, const void* src) {
    asm volatile("cp.async.ca.shared.global [%0], [%1], 4;" :: "r"(dst), "l"(src));
}
#define CP_COMMIT() asm volatile("cp.async.commit_group;" ::: "memory")
#define CP_WAIT0()  asm volatile("cp.async.wait_group 0;" ::: "memory")
#define CP_WAIT1()  asm volatile("cp.async.wait_group 1;" ::: "memory")

__device__ __forceinline__ void ldsm4(uint32_t* r, uint32_t addr) {
    asm volatile("ldmatrix.sync.aligned.m8n8.x4.shared.b16 {%0,%1,%2,%3}, [%4];"
                 : "=r"(r[0]), "=r"(r[1]), "=r"(r[2]), "=r"(r[3]) : "r"(addr));
}
__device__ __forceinline__ void ldsm4t(uint32_t* r, uint32_t addr) {
    asm volatile("ldmatrix.sync.aligned.m8n8.x4.trans.shared.b16 {%0,%1,%2,%3}, [%4];"
                 : "=r"(r[0]), "=r"(r[1]), "=r"(r[2]), "=r"(r[3]) : "r"(addr));
}
__device__ __forceinline__ void mma_f16(float* c, const uint32_t* a, const uint32_t* b) {
    asm volatile("mma.sync.aligned.m16n8k16.row.col.f32.f16.f16.f32 "
                 "{%0,%1,%2,%3}, {%4,%5,%6,%7}, {%8,%9}, {%0,%1,%2,%3};"
                 : "+f"(c[0]), "+f"(c[1]), "+f"(c[2]), "+f"(c[3])
                 : "r"(a[0]), "r"(a[1]), "r"(a[2]), "r"(a[3]), "r"(b[0]), "r"(b[1]));
}
__device__ __forceinline__ float ex2f(float x) {
    float r; asm("ex2.approx.f32 %0, %1;" : "=f"(r) : "f"(x)); return r;
}
// split pair (v0,v1) -> packed fp16 hi pair + fp16 lo-residual pair
__device__ __forceinline__ void split2h(float v0, float v1, uint32_t& hi, uint32_t& lo) {
    __half h0 = __float2half_rn(v0), h1 = __float2half_rn(v1);
    __half2 hp = __halves2half2(h0, h1);
    hi = *(uint32_t*)&hp;
    __half2 lp = __floats2half2_rn(v0 - __half2float(h0), v1 - __half2float(h1));
    lo = *(uint32_t*)&lp;
}
__device__ __forceinline__ uint32_t pack2h(float v0, float v1) {
    __half2 p = __floats2half2_rn(v0, v1);
    return *(uint32_t*)&p;
}

// ---------------- prep ----------------
__global__ void split_x_kernel(const float* __restrict__ src) {
    for (size_t i = (size_t)blockIdx.x * blockDim.x + threadIdx.x; i < (size_t)MTOK * D_MODEL;
         i += (size_t)gridDim.x * blockDim.x) {
        float v = src[i];
        __half h = __float2half_rn(v);
        g_xh[i] = h;
        g_xl[i] = __float2half_rn(v - __half2float(h));
    }
}
__global__ void split_w_kernel(const float* __restrict__ w0, const float* __restrict__ w1,
                               const float* __restrict__ w2, const float* __restrict__ w3) {
    int idx = blockIdx.y;
    const float* src = (idx == 0) ? w0 : (idx == 1) ? w1 : (idx == 2) ? w2 : w3;
    size_t off = (size_t)idx * 1048576;
    for (size_t i = (size_t)blockIdx.x * blockDim.x + threadIdx.x; i < 1048576;
         i += (size_t)gridDim.x * blockDim.x) {
        g_w[off + i] = __float2half_rn(src[i]);
    }
}

// ---------------- projection GEMM: 128m x 128n, A fp16 2-limb x B fp16 single ----
// OPROJ=0: QKV via blockIdx.z (0:Q scaled -> hi/lo, 1:K -> single, 2:V -> single)
// OPROJ=1: O projection (ctx hi/lo @ Wo^T + bias) -> fp32 out
// stage: Ah(10240) + Al(10240) + B(10240) = 30720B; 2 stages; 2 CTAs/SM
#define PST 30720

template<int OPROJ>
__global__ void __launch_bounds__(256, 2)
proj_kernel(const float* __restrict__ bias, float* __restrict__ out)
{
    extern __shared__ char smem[];
    const uint32_t sb = su32(smem);
    const int tid = threadIdx.x;
    const int lane = tid & 31, wid = tid >> 5;
    const int wm = wid >> 2, wn = wid & 3;
    const int g = lane >> 2, tig = lane & 3;
    const int m0 = blockIdx.x * 128, n0 = blockIdx.y * 128;
    const int mode = OPROJ ? 3 : (int)blockIdx.z;

    const __half* Ah = OPROJ ? g_ch : g_xh;
    const __half* Al = OPROJ ? g_cl : g_xl;
    const __half* B  = g_w + (size_t)mode * 1048576;

    float acc[4][4][4];
#pragma unroll
    for (int i = 0; i < 4; i++)
#pragma unroll
        for (int j = 0; j < 4; j++)
#pragma unroll
            for (int e = 0; e < 4; e++) acc[i][j][e] = 0.0f;

    auto load_stage = [&](int kt, int buf) {
        uint32_t base = sb + buf * PST;
#pragma unroll
        for (int t = 0; t < 6; t++) {
            int vi = tid + t * 256;       // 0..1535
            if (vi < 1024) {
                int tile = vi >> 9;       // 0 Ah, 1 Al
                int row = (vi >> 2) & 127;
                int ch = vi & 3;
                const __half* src = (tile ? Al : Ah) + (size_t)(m0 + row) * 1024 + kt + ch * 8;
                cpa16(base + tile * 10240 + row * 80 + ch * 16, src);
            } else {
                int vi2 = vi - 1024;      // 0..511
                int row = (vi2 >> 2) & 127;
                int ch = vi2 & 3;
                cpa16(base + 20480 + row * 80 + ch * 16,
                      B + (size_t)(n0 + row) * 1024 + kt + ch * 8);
            }
        }
        CP_COMMIT();
    };

    load_stage(0, 0);
    for (int s = 0; s < 32; s++) {
        if (s < 31) { load_stage((s + 1) * 32, (s + 1) & 1); CP_WAIT1(); }
        else CP_WAIT0();
        __syncthreads();
        uint32_t base = sb + (s & 1) * PST;
#pragma unroll
        for (int ks = 0; ks < 2; ks++) {
            uint32_t afh[4][4], afl[4][4];
#pragma unroll
            for (int mf = 0; mf < 4; mf++) {
                uint32_t a = base + (uint32_t)(wm * 64 + mf * 16 + (lane & 15)) * 80
                           + (ks * 16 + (lane >> 4) * 8) * 2;
                ldsm4(afh[mf], a);
                ldsm4(afl[mf], a + 10240);
            }
#pragma unroll
            for (int g2 = 0; g2 < 2; g2++) {
                uint32_t bf[4];
                uint32_t a = base + 20480
                           + (uint32_t)(wn * 32 + g2 * 16 + (lane & 7) + ((lane >> 4) << 3)) * 80
                           + (ks * 16 + ((lane >> 3) & 1) * 8) * 2;
                ldsm4(bf, a);
#pragma unroll
                for (int mf = 0; mf < 4; mf++)
#pragma unroll
                    for (int j = 0; j < 2; j++) {
                        float* c = acc[mf][g2 * 2 + j];
                        mma_f16(c, afh[mf], &bf[j * 2]);
                        mma_f16(c, afl[mf], &bf[j * 2]);
                    }
            }
        }
        __syncthreads();
    }

    // epilogue
    const float scale = (mode == 0) ? QSCALE : 1.0f;
#pragma unroll
    for (int mf = 0; mf < 4; mf++) {
#pragma unroll
        for (int half = 0; half < 2; half++) {
            int m = m0 + wm * 64 + mf * 16 + g + half * 8;
#pragma unroll
            for (int nf = 0; nf < 4; nf++) {
                int n = n0 + wn * 32 + nf * 8 + 2 * tig;
                float v0 = acc[mf][nf][half * 2] * scale;
                float v1 = acc[mf][nf][half * 2 + 1] * scale;
                if (OPROJ) {
                    float2 o = make_float2(v0 + bias[n], v1 + bias[n + 1]);
                    *(float2*)(out + (size_t)m * 1024 + n) = o;
                } else {
                    int b = m >> 11, ss = m & 2047;
                    int h = n >> 6, d = n & 63;
                    size_t addr = (((size_t)(b * 16 + h) * 2048) + ss) * 64 + d;
                    if (mode == 0) {
                        uint32_t hi, lo;
                        split2h(v0, v1, hi, lo);
                        *(uint32_t*)(g_qh + addr) = hi;
                        *(uint32_t*)(g_ql + addr) = lo;
                    } else {
                        __half* D = (mode == 1) ? g_k : g_v;
                        *(uint32_t*)(D + addr) = pack2h(v0, v1);
                    }
                }
            }
        }
    }
}

// ---------------- attention: fp16 2-pass, half-column passes, double-buffered ------
// 8 warps x 16 q-rows, 256 thr, 2 CTAs/SM.
// Q hi/lo tiles 128x64 fp16 stride 144B (18432B each). KV stage: K(18432)+V(18432).
// SMEM: QH 0, QL 18432; KV stage s at 36864+s*36864; bias at 110592+s*1024. Tot 112640.
#define AT_TS  18432
#define AT_QH  0
#define AT_QL  18432
#define AT_KV  36864
#define AT_KVS 36864
#define AT_SB  110592
#define AT_SMEM 112640

__global__ void __launch_bounds__(256, 2)
attn_kernel(const float* __restrict__ bias_table)
{
    extern __shared__ char smem[];
    const uint32_t sb = su32(smem);
    const int tid = threadIdx.x;
    const int lane = tid & 31, w = tid >> 5;
    const int g = lane >> 2, tig = lane & 3;
    const int bh = blockIdx.y;
    const int b = bh >> 4, h = bh & 15;
    const int q0 = blockIdx.x * 128;

    // Q tiles hi/lo: 2048 x 16B chunks
#pragma unroll
    for (int t2 = 0; t2 < 8; t2++) {
        int vi = tid + t2 * 256;
        int half = vi >> 10;
        int row = (vi >> 3) & 127;
        int ch = vi & 7;
        const __half* src = (half ? g_ql : g_qh)
            + ((size_t)bh * 2048 + q0 + row) * 64 + ch * 8;
        cpa16(sb + (half ? AT_QL : AT_QH) + row * 144 + ch * 16, src);
    }

    auto issue_kv = [&](int buf, int k0) {
        uint32_t base = sb + AT_KV + buf * AT_KVS;
#pragma unroll
        for (int u = 0; u < 8; u++) {
            int vi = tid + u * 256;
            int tile = vi >> 10;          // 0 K, 1 V
            int row = (vi >> 3) & 127;
            int ch = vi & 7;
            const __half* src = (tile ? g_v : g_k)
                + ((size_t)bh * 2048 + k0 + row) * 64 + ch * 8;
            cpa16(base + tile * AT_TS + row * 144 + ch * 16, src);
        }
        if (tid < 255)
            cpa4(sb + AT_SB + buf * 1024 + tid * 4,
                 bias_table + (size_t)(q0 - k0 + 1920 + tid) * 16 + h);
    };

    issue_kv(0, 0);
    CP_COMMIT();   // group: Q + KV0

    float oacc[8][4];
#pragma unroll
    for (int i = 0; i < 8; i++)
#pragma unroll
        for (int e = 0; e < 4; e++) oacc[i][e] = 0.0f;
    float lsumA = 0.0f, lsumB = 0.0f;

    const int d0 = w * 16 + g - 2 * tig + 127;

    for (int t = 0; t < 16; t++) {
        if (t < 15) { issue_kv((t + 1) & 1, (t + 1) * 128); CP_COMMIT(); CP_WAIT1(); }
        else CP_WAIT0();
        __syncthreads();

        const uint32_t kvb = sb + AT_KV + (t & 1) * AT_KVS;
        const float* sbias = (const float*)(smem + AT_SB + (t & 1) * 1024);

#pragma unroll
        for (int half = 0; half < 2; half++) {
            // ---- S(half) = Q @ K[half]^T (log2-scaled), 64 cols ----
            float sacc[8][4];
#pragma unroll
            for (int i = 0; i < 8; i++)
#pragma unroll
                for (int e = 0; e < 4; e++) sacc[i][e] = 0.0f;
#pragma unroll
            for (int ks = 0; ks < 4; ks++) {
                uint32_t qfh[4], qfl[4];
                {
                    uint32_t a = sb + AT_QH + (uint32_t)(w * 16 + (lane & 15)) * 144
                               + (ks * 16 + (lane >> 4) * 8) * 2;
                    ldsm4(qfh, a);
                    ldsm4(qfl, a + AT_TS);
                }
                uint32_t kf[4][4];
#pragma unroll
                for (int g2 = 0; g2 < 4; g2++) {
                    uint32_t a = kvb
                        + (uint32_t)(half * 64 + g2 * 16 + (lane & 7) + ((lane >> 4) << 3)) * 144
                        + (ks * 16 + ((lane >> 3) & 1) * 8) * 2;
                    ldsm4(kf[g2], a);
                }
#pragma unroll
                for (int nf2 = 0; nf2 < 8; nf2++) {
                    float* c = sacc[nf2];
                    const uint32_t* bp = &kf[nf2 >> 1][(nf2 & 1) * 2];
                    mma_f16(c, qfh, bp);
                    mma_f16(c, qfl, bp);
                }
            }

            // ---- P(half) = 2^(S + bias*log2e): C-frag -> A-frag, fp16 hi/lo ----
            uint32_t pfh[4][4], pfl[4][4];
#pragma unroll
            for (int ks2 = 0; ks2 < 4; ks2++) {
#pragma unroll
                for (int j = 0; j < 2; j++) {
                    int nf2 = 2 * ks2 + j;
                    float* c = sacc[nf2];
                    int idx = d0 - (half * 8 + nf2) * 8;
                    float p0 = ex2f(fmaf(sbias[idx],     LOG2E, c[0]));
                    float p1 = ex2f(fmaf(sbias[idx - 1], LOG2E, c[1]));
                    float p2 = ex2f(fmaf(sbias[idx + 8], LOG2E, c[2]));
                    float p3 = ex2f(fmaf(sbias[idx + 7], LOG2E, c[3]));
                    lsumA += p0 + p1;
                    lsumB += p2 + p3;
                    split2h(p0, p1, pfh[ks2][j * 2 + 0], pfl[ks2][j * 2 + 0]);
                    split2h(p2, p3, pfh[ks2][j * 2 + 1], pfl[ks2][j * 2 + 1]);
                }
            }

            // ---- O += P(half) @ V[half] ----
            const uint32_t vb = kvb + AT_TS;
#pragma unroll
            for (int ks2 = 0; ks2 < 4; ks2++) {
                uint32_t vf[4][4];
#pragma unroll
                for (int dblk = 0; dblk < 4; dblk++) {
                    uint32_t a = vb
                        + (uint32_t)(half * 64 + ks2 * 16 + (lane & 7) + ((lane >> 3) & 1) * 8) * 144
                        + (dblk * 16 + ((lane >> 4) << 3)) * 2;
                    ldsm4t(vf[dblk], a);
                }
#pragma unroll
                for (int dblk = 0; dblk < 4; dblk++)
#pragma unroll
                    for (int sub = 0; sub < 2; sub++) {
                        float* o = oacc[dblk * 2 + sub];
                        mma_f16(o, pfh[ks2], &vf[dblk][sub * 2]);
                        mma_f16(o, pfl[ks2], &vf[dblk][sub * 2]);
                    }
            }
        }
        __syncthreads();
    }

    // ---- row-sum reduce within quad, epilogue ----
    lsumA += __shfl_xor_sync(0xffffffffu, lsumA, 1);
    lsumA += __shfl_xor_sync(0xffffffffu, lsumA, 2);
    lsumB += __shfl_xor_sync(0xffffffffu, lsumB, 1);
    lsumB += __shfl_xor_sync(0xffffffffu, lsumB, 2);
    const float inv0 = 1.0f / lsumA;
    const float inv1 = 1.0f / lsumB;
    const int row0 = q0 + w * 16 + g;
    const size_t base0 = (size_t)(b * 2048 + row0) * 1024 + h * 64;
    const size_t base1 = (size_t)(b * 2048 + row0 + 8) * 1024 + h * 64;
#pragma unroll
    for (int nfd = 0; nfd < 8; nfd++) {
        int d = nfd * 8 + 2 * tig;
        uint32_t hi, lo;
        split2h(oacc[nfd][0] * inv0, oacc[nfd][1] * inv0, hi, lo);
        *(uint32_t*)(g_ch + base0 + d) = hi;
        *(uint32_t*)(g_cl + base0 + d) = lo;
        split2h(oacc[nfd][2] * inv1, oacc[nfd][3] * inv1, hi, lo);
        *(uint32_t*)(g_ch + base1 + d) = hi;
        *(uint32_t*)(g_cl + base1 + d) = lo;
    }
}

// ---------------- launch ----------------
extern "C" void kernel_launch(void* const* d_in, const int* in_sizes, int n_in,
                              void* d_out, int out_size)
{
    const float* x  = (const float*)d_in[0];
    const float* Wq = (const float*)d_in[1];
    const float* Wk = (const float*)d_in[2];
    const float* Wv = (const float*)d_in[3];
    const float* Wo = (const float*)d_in[4];
    const float* bo = (const float*)d_in[5];
    const float* bt = (const float*)d_in[6];
    float* out = (float*)d_out;

    cudaFuncSetAttribute(proj_kernel<0>, cudaFuncAttributeMaxDynamicSharedMemorySize, 2 * PST);
    cudaFuncSetAttribute(proj_kernel<1>, cudaFuncAttributeMaxDynamicSharedMemorySize, 2 * PST);
    cudaFuncSetAttribute(attn_kernel,    cudaFuncAttributeMaxDynamicSharedMemorySize, AT_SMEM);

    split_x_kernel<<<2048, 256>>>(x);
    split_w_kernel<<<dim3(256, 4), 256>>>(Wq, Wk, Wv, Wo);

    proj_kernel<0><<<dim3(64, 8, 3), 256, 2 * PST>>>(nullptr, nullptr);

    attn_kernel<<<dim3(16, 64), 256, AT_SMEM>>>(bt);

    proj_kernel<1><<<dim3(64, 8), 256, 2 * PST>>>(bo, out);
}

// round 15
// speedup vs baseline: 2.2747x; 1.0632x over previous
#include <cuda_runtime.h>
#include <cuda_fp16.h>
#include <stdint.h>

#define D_MODEL 1024
#define NHEADS  16
#define HD      64
#define BATCH   4
#define SEQ     2048
#define BH      64
#define MTOK    8192
#define QSCALE  0.18033688011112042f   // 0.125 * log2(e)
#define LOG2E   1.4426950408889634f

// ---------------- scratch globals (allocation-free) ----------------
__device__ __half g_q[8388608];          // Q fp16 (scaled) [bh][s][d]
__device__ __half g_k[8388608];          // K fp16
__device__ __half g_v[8388608];          // V fp16
__device__ __half g_x[8388608];          // x fp16
__device__ __half g_w[4194304];          // 4 x W fp16
__device__ __half g_c[8388608];          // ctx fp16

// ---------------- helpers ----------------
__device__ __forceinline__ uint32_t su32(const void* p) {
    uint32_t a;
    asm("{ .reg .u64 t; cvta.to.shared.u64 t, %1; cvt.u32.u64 %0, t; }" : "=r"(a) : "l"(p));
    return a;
}
__device__ __forceinline__ void cpa16(uint32_t dst, const void* src) {
    asm volatile("cp.async.cg.shared.global [%0], [%1], 16;" :: "r"(dst), "l"(src));
}
__device__ __forceinline__ void cpa4(uint32_t dst, const void* src) {
    asm volatile("cp.async.ca.shared.global [%0], [%1], 4;" :: "r"(dst), "l"(src));
}
#define CP_COMMIT() asm volatile("cp.async.commit_group;" ::: "memory")
#define CP_WAIT0()  asm volatile("cp.async.wait_group 0;" ::: "memory")
#define CP_WAIT1()  asm volatile("cp.async.wait_group 1;" ::: "memory")

__device__ __forceinline__ void ldsm4(uint32_t* r, uint32_t addr) {
    asm volatile("ldmatrix.sync.aligned.m8n8.x4.shared.b16 {%0,%1,%2,%3}, [%4];"
                 : "=r"(r[0]), "=r"(r[1]), "=r"(r[2]), "=r"(r[3]) : "r"(addr));
}
__device__ __forceinline__ void ldsm4t(uint32_t* r, uint32_t addr) {
    asm volatile("ldmatrix.sync.aligned.m8n8.x4.trans.shared.b16 {%0,%1,%2,%3}, [%4];"
                 : "=r"(r[0]), "=r"(r[1]), "=r"(r[2]), "=r"(r[3]) : "r"(addr));
}
__device__ __forceinline__ void mma_f16(float* c, const uint32_t* a, const uint32_t* b) {
    asm volatile("mma.sync.aligned.m16n8k16.row.col.f32.f16.f16.f32 "
                 "{%0,%1,%2,%3}, {%4,%5,%6,%7}, {%8,%9}, {%0,%1,%2,%3};"
                 : "+f"(c[0]), "+f"(c[1]), "+f"(c[2]), "+f"(c[3])
                 : "r"(a[0]), "r"(a[1]), "r"(a[2]), "r"(a[3]), "r"(b[0]), "r"(b[1]));
}
__device__ __forceinline__ float ex2f(float x) {
    float r; asm("ex2.approx.f32 %0, %1;" : "=f"(r) : "f"(x)); return r;
}
__device__ __forceinline__ uint32_t pack2h(float v0, float v1) {
    __half2 p = __floats2half2_rn(v0, v1);
    return *(uint32_t*)&p;
}

// ---------------- prep ----------------
__global__ void split_x_kernel(const float* __restrict__ src) {
    for (size_t i = (size_t)blockIdx.x * blockDim.x + threadIdx.x; i < (size_t)MTOK * D_MODEL;
         i += (size_t)gridDim.x * blockDim.x)
        g_x[i] = __float2half_rn(src[i]);
}
__global__ void split_w_kernel(const float* __restrict__ w0, const float* __restrict__ w1,
                               const float* __restrict__ w2, const float* __restrict__ w3) {
    int idx = blockIdx.y;
    const float* src = (idx == 0) ? w0 : (idx == 1) ? w1 : (idx == 2) ? w2 : w3;
    size_t off = (size_t)idx * 1048576;
    for (size_t i = (size_t)blockIdx.x * blockDim.x + threadIdx.x; i < 1048576;
         i += (size_t)gridDim.x * blockDim.x)
        g_w[off + i] = __float2half_rn(src[i]);
}

// ---------------- projection GEMM: 128m x 128n, single-pass fp16 ----------
// OPROJ=0: QKV via blockIdx.z (0:Q scaled, 1:K, 2:V) -> fp16 scratch
// OPROJ=1: O projection (ctx @ Wo^T + bias) -> fp32 out
// stage: A(10240) + B(10240) = 20480B; 2 stages; 2 CTAs/SM
#define PST 20480

template<int OPROJ>
__global__ void __launch_bounds__(256, 2)
proj_kernel(const float* __restrict__ bias, float* __restrict__ out)
{
    extern __shared__ char smem[];
    const uint32_t sb = su32(smem);
    const int tid = threadIdx.x;
    const int lane = tid & 31, wid = tid >> 5;
    const int wm = wid >> 2, wn = wid & 3;
    const int g = lane >> 2, tig = lane & 3;
    const int m0 = blockIdx.x * 128, n0 = blockIdx.y * 128;
    const int mode = OPROJ ? 3 : (int)blockIdx.z;

    const __half* A = OPROJ ? g_c : g_x;
    const __half* B = g_w + (size_t)mode * 1048576;

    float acc[4][4][4];
#pragma unroll
    for (int i = 0; i < 4; i++)
#pragma unroll
        for (int j = 0; j < 4; j++)
#pragma unroll
            for (int e = 0; e < 4; e++) acc[i][j][e] = 0.0f;

    auto load_stage = [&](int kt, int buf) {
        uint32_t base = sb + buf * PST;
#pragma unroll
        for (int t = 0; t < 4; t++) {
            int vi = tid + t * 256;       // 0..1023
            int tile = vi >> 9;           // 0 A, 1 B
            int row = (vi >> 2) & 127;
            int ch = vi & 3;
            const __half* src = (tile ? B + (size_t)(n0 + row) * 1024
                                      : A + (size_t)(m0 + row) * 1024) + kt + ch * 8;
            cpa16(base + tile * 10240 + row * 80 + ch * 16, src);
        }
        CP_COMMIT();
    };

    load_stage(0, 0);
    for (int s = 0; s < 32; s++) {
        if (s < 31) { load_stage((s + 1) * 32, (s + 1) & 1); CP_WAIT1(); }
        else CP_WAIT0();
        __syncthreads();
        uint32_t base = sb + (s & 1) * PST;
#pragma unroll
        for (int ks = 0; ks < 2; ks++) {
            uint32_t af[4][4];
#pragma unroll
            for (int mf = 0; mf < 4; mf++) {
                uint32_t a = base + (uint32_t)(wm * 64 + mf * 16 + (lane & 15)) * 80
                           + (ks * 16 + (lane >> 4) * 8) * 2;
                ldsm4(af[mf], a);
            }
#pragma unroll
            for (int g2 = 0; g2 < 2; g2++) {
                uint32_t bf[4];
                uint32_t a = base + 10240
                           + (uint32_t)(wn * 32 + g2 * 16 + (lane & 7) + ((lane >> 4) << 3)) * 80
                           + (ks * 16 + ((lane >> 3) & 1) * 8) * 2;
                ldsm4(bf, a);
#pragma unroll
                for (int mf = 0; mf < 4; mf++)
#pragma unroll
                    for (int j = 0; j < 2; j++)
                        mma_f16(acc[mf][g2 * 2 + j], af[mf], &bf[j * 2]);
            }
        }
        __syncthreads();
    }

    // epilogue
    const float scale = (mode == 0) ? QSCALE : 1.0f;
#pragma unroll
    for (int mf = 0; mf < 4; mf++) {
#pragma unroll
        for (int half = 0; half < 2; half++) {
            int m = m0 + wm * 64 + mf * 16 + g + half * 8;
#pragma unroll
            for (int nf = 0; nf < 4; nf++) {
                int n = n0 + wn * 32 + nf * 8 + 2 * tig;
                float v0 = acc[mf][nf][half * 2] * scale;
                float v1 = acc[mf][nf][half * 2 + 1] * scale;
                if (OPROJ) {
                    float2 o = make_float2(v0 + bias[n], v1 + bias[n + 1]);
                    *(float2*)(out + (size_t)m * 1024 + n) = o;
                } else {
                    int b = m >> 11, ss = m & 2047;
                    int h = n >> 6, d = n & 63;
                    size_t addr = (((size_t)(b * 16 + h) * 2048) + ss) * 64 + d;
                    __half* D = (mode == 0) ? g_q : (mode == 1) ? g_k : g_v;
                    *(uint32_t*)(D + addr) = pack2h(v0, v1);
                }
            }
        }
    }
}

// ---------------- attention: single-pass fp16, half-column passes, double-buffered ----
// 8 warps x 16 q-rows, 256 thr, 2 CTAs/SM.
// Q tile 128x64 fp16 stride 144B (18432B). KV stage: K(18432)+V(18432).
// SMEM: Q 0; KV stage s at 18432+s*36864; bias at 92160+s*1024. Total 94208.
#define AT_TS  18432
#define AT_Q   0
#define AT_KV  18432
#define AT_KVS 36864
#define AT_SB  92160
#define AT_SMEM 94208

__global__ void __launch_bounds__(256, 2)
attn_kernel(const float* __restrict__ bias_table)
{
    extern __shared__ char smem[];
    const uint32_t sb = su32(smem);
    const int tid = threadIdx.x;
    const int lane = tid & 31, w = tid >> 5;
    const int g = lane >> 2, tig = lane & 3;
    const int bh = blockIdx.y;
    const int b = bh >> 4, h = bh & 15;
    const int q0 = blockIdx.x * 128;

    // Q tile: 1024 x 16B chunks
#pragma unroll
    for (int t2 = 0; t2 < 4; t2++) {
        int vi = tid + t2 * 256;
        int row = (vi >> 3) & 127;
        int ch = vi & 7;
        cpa16(sb + AT_Q + row * 144 + ch * 16,
              g_q + ((size_t)bh * 2048 + q0 + row) * 64 + ch * 8);
    }

    auto issue_kv = [&](int buf, int k0) {
        uint32_t base = sb + AT_KV + buf * AT_KVS;
#pragma unroll
        for (int u = 0; u < 8; u++) {
            int vi = tid + u * 256;
            int tile = vi >> 10;          // 0 K, 1 V
            int row = (vi >> 3) & 127;
            int ch = vi & 7;
            const __half* src = (tile ? g_v : g_k)
                + ((size_t)bh * 2048 + k0 + row) * 64 + ch * 8;
            cpa16(base + tile * AT_TS + row * 144 + ch * 16, src);
        }
        if (tid < 255)
            cpa4(sb + AT_SB + buf * 1024 + tid * 4,
                 bias_table + (size_t)(q0 - k0 + 1920 + tid) * 16 + h);
    };

    issue_kv(0, 0);
    CP_COMMIT();   // group: Q + KV0

    float oacc[8][4];
#pragma unroll
    for (int i = 0; i < 8; i++)
#pragma unroll
        for (int e = 0; e < 4; e++) oacc[i][e] = 0.0f;
    float lsumA = 0.0f, lsumB = 0.0f;

    const int d0 = w * 16 + g - 2 * tig + 127;

    for (int t = 0; t < 16; t++) {
        if (t < 15) { issue_kv((t + 1) & 1, (t + 1) * 128); CP_COMMIT(); CP_WAIT1(); }
        else CP_WAIT0();
        __syncthreads();

        const uint32_t kvb = sb + AT_KV + (t & 1) * AT_KVS;
        const float* sbias = (const float*)(smem + AT_SB + (t & 1) * 1024);

#pragma unroll
        for (int half = 0; half < 2; half++) {
            // ---- S(half) = Q @ K[half]^T (log2-scaled), 64 cols ----
            float sacc[8][4];
#pragma unroll
            for (int i = 0; i < 8; i++)
#pragma unroll
                for (int e = 0; e < 4; e++) sacc[i][e] = 0.0f;
#pragma unroll
            for (int ks = 0; ks < 4; ks++) {
                uint32_t qf[4];
                {
                    uint32_t a = sb + AT_Q + (uint32_t)(w * 16 + (lane & 15)) * 144
                               + (ks * 16 + (lane >> 4) * 8) * 2;
                    ldsm4(qf, a);
                }
                uint32_t kf[4][4];
#pragma unroll
                for (int g2 = 0; g2 < 4; g2++) {
                    uint32_t a = kvb
                        + (uint32_t)(half * 64 + g2 * 16 + (lane & 7) + ((lane >> 4) << 3)) * 144
                        + (ks * 16 + ((lane >> 3) & 1) * 8) * 2;
                    ldsm4(kf[g2], a);
                }
#pragma unroll
                for (int nf2 = 0; nf2 < 8; nf2++)
                    mma_f16(sacc[nf2], qf, &kf[nf2 >> 1][(nf2 & 1) * 2]);
            }

            // ---- P(half) = 2^(S + bias*log2e): C-frag -> A-frag, single fp16 ----
            uint32_t pf[4][4];
#pragma unroll
            for (int ks2 = 0; ks2 < 4; ks2++) {
#pragma unroll
                for (int j = 0; j < 2; j++) {
                    int nf2 = 2 * ks2 + j;
                    float* c = sacc[nf2];
                    int idx = d0 - (half * 8 + nf2) * 8;
                    float p0 = ex2f(fmaf(sbias[idx],     LOG2E, c[0]));
                    float p1 = ex2f(fmaf(sbias[idx - 1], LOG2E, c[1]));
                    float p2 = ex2f(fmaf(sbias[idx + 8], LOG2E, c[2]));
                    float p3 = ex2f(fmaf(sbias[idx + 7], LOG2E, c[3]));
                    lsumA += p0 + p1;
                    lsumB += p2 + p3;
                    pf[ks2][j * 2 + 0] = pack2h(p0, p1);
                    pf[ks2][j * 2 + 1] = pack2h(p2, p3);
                }
            }

            // ---- O += P(half) @ V[half] ----
            const uint32_t vb = kvb + AT_TS;
#pragma unroll
            for (int ks2 = 0; ks2 < 4; ks2++) {
                uint32_t vf[4][4];
#pragma unroll
                for (int dblk = 0; dblk < 4; dblk++) {
                    uint32_t a = vb
                        + (uint32_t)(half * 64 + ks2 * 16 + (lane & 7) + ((lane >> 3) & 1) * 8) * 144
                        + (dblk * 16 + ((lane >> 4) << 3)) * 2;
                    ldsm4t(vf[dblk], a);
                }
#pragma unroll
                for (int dblk = 0; dblk < 4; dblk++)
#pragma unroll
                    for (int sub = 0; sub < 2; sub++)
                        mma_f16(oacc[dblk * 2 + sub], pf[ks2], &vf[dblk][sub * 2]);
            }
        }
        __syncthreads();
    }

    // ---- row-sum reduce within quad, epilogue ----
    lsumA += __shfl_xor_sync(0xffffffffu, lsumA, 1);
    lsumA += __shfl_xor_sync(0xffffffffu, lsumA, 2);
    lsumB += __shfl_xor_sync(0xffffffffu, lsumB, 1);
    lsumB += __shfl_xor_sync(0xffffffffu, lsumB, 2);
    const float inv0 = 1.0f / lsumA;
    const float inv1 = 1.0f / lsumB;
    const int row0 = q0 + w * 16 + g;
    const size_t base0 = (size_t)(b * 2048 + row0) * 1024 + h * 64;
    const size_t base1 = (size_t)(b * 2048 + row0 + 8) * 1024 + h * 64;
#pragma unroll
    for (int nfd = 0; nfd < 8; nfd++) {
        int d = nfd * 8 + 2 * tig;
        *(uint32_t*)(g_c + base0 + d) = pack2h(oacc[nfd][0] * inv0, oacc[nfd][1] * inv0);
        *(uint32_t*)(g_c + base1 + d) = pack2h(oacc[nfd][2] * inv1, oacc[nfd][3] * inv1);
    }
}

// ---------------- launch ----------------
extern "C" void kernel_launch(void* const* d_in, const int* in_sizes, int n_in,
                              void* d_out, int out_size)
{
    const float* x  = (const float*)d_in[0];
    const float* Wq = (const float*)d_in[1];
    const float* Wk = (const float*)d_in[2];
    const float* Wv = (const float*)d_in[3];
    const float* Wo = (const float*)d_in[4];
    const float* bo = (const float*)d_in[5];
    const float* bt = (const float*)d_in[6];
    float* out = (float*)d_out;

    cudaFuncSetAttribute(proj_kernel<0>, cudaFuncAttributeMaxDynamicSharedMemorySize, 2 * PST);
    cudaFuncSetAttribute(proj_kernel<1>, cudaFuncAttributeMaxDynamicSharedMemorySize, 2 * PST);
    cudaFuncSetAttribute(attn_kernel,    cudaFuncAttributeMaxDynamicSharedMemorySize, AT_SMEM);

    split_x_kernel<<<2048, 256>>>(x);
    split_w_kernel<<<dim3(256, 4), 256>>>(Wq, Wk, Wv, Wo);

    proj_kernel<0><<<dim3(64, 8, 3), 256, 2 * PST>>>(nullptr, nullptr);

    attn_kernel<<<dim3(16, 64), 256, AT_SMEM>>>(bt);

    proj_kernel<1><<<dim3(64, 8), 256, 2 * PST>>>(bo, out);
}

// round 16
// speedup vs baseline: 3.9084x; 1.7182x over previous
#include <cuda_runtime.h>
#include <cuda_fp16.h>
#include <stdint.h>

#define D_MODEL 1024
#define NHEADS  16
#define HD      64
#define BATCH   4
#define SEQ     2048
#define BH      64
#define MTOK    8192
#define QSCALE  0.18033688011112042f   // 0.125 * log2(e)
#define LOG2E   1.4426950408889634f

// ---------------- scratch globals (allocation-free) ----------------
__device__ __half g_q[8388608];          // Q fp16 (scaled) [bh][s][d]
__device__ __half g_k[8388608];          // K fp16
__device__ __half g_v[8388608];          // V fp16
__device__ __half g_x[8388608];          // x fp16
__device__ __half g_w[4194304];          // 4 x W fp16
__device__ __half g_c[8388608];          // ctx fp16

// ---------------- helpers ----------------
__device__ __forceinline__ uint32_t su32(const void* p) {
    uint32_t a;
    asm("{ .reg .u64 t; cvta.to.shared.u64 t, %1; cvt.u32.u64 %0, t; }" : "=r"(a) : "l"(p));
    return a;
}
__device__ __forceinline__ void cpa16(uint32_t dst, const void* src) {
    asm volatile("cp.async.cg.shared.global [%0], [%1], 16;" :: "r"(dst), "l"(src));
}
__device__ __forceinline__ void cpa4(uint32_t dst, const void* src) {
    asm volatile("cp.async.ca.shared.global [%0], [%1], 4;" :: "r"(dst), "l"(src));
}
#define CP_COMMIT() asm volatile("cp.async.commit_group;" ::: "memory")
#define CP_WAIT0()  asm volatile("cp.async.wait_group 0;" ::: "memory")
#define CP_WAIT1()  asm volatile("cp.async.wait_group 1;" ::: "memory")

__device__ __forceinline__ void ldsm4(uint32_t* r, uint32_t addr) {
    asm volatile("ldmatrix.sync.aligned.m8n8.x4.shared.b16 {%0,%1,%2,%3}, [%4];"
                 : "=r"(r[0]), "=r"(r[1]), "=r"(r[2]), "=r"(r[3]) : "r"(addr));
}
__device__ __forceinline__ void ldsm4t(uint32_t* r, uint32_t addr) {
    asm volatile("ldmatrix.sync.aligned.m8n8.x4.trans.shared.b16 {%0,%1,%2,%3}, [%4];"
                 : "=r"(r[0]), "=r"(r[1]), "=r"(r[2]), "=r"(r[3]) : "r"(addr));
}
__device__ __forceinline__ void mma_f16(float* c, const uint32_t* a, const uint32_t* b) {
    asm volatile("mma.sync.aligned.m16n8k16.row.col.f32.f16.f16.f32 "
                 "{%0,%1,%2,%3}, {%4,%5,%6,%7}, {%8,%9}, {%0,%1,%2,%3};"
                 : "+f"(c[0]), "+f"(c[1]), "+f"(c[2]), "+f"(c[3])
                 : "r"(a[0]), "r"(a[1]), "r"(a[2]), "r"(a[3]), "r"(b[0]), "r"(b[1]));
}
__device__ __forceinline__ float ex2f(float x) {
    float r; asm("ex2.approx.f32 %0, %1;" : "=f"(r) : "f"(x)); return r;
}
__device__ __forceinline__ uint32_t pack2h(float v0, float v1) {
    __half2 p = __floats2half2_rn(v0, v1);
    return *(uint32_t*)&p;
}

// ---------------- prep ----------------
__global__ void split_x_kernel(const float* __restrict__ src) {
    for (size_t i = (size_t)blockIdx.x * blockDim.x + threadIdx.x; i < (size_t)MTOK * D_MODEL;
         i += (size_t)gridDim.x * blockDim.x)
        g_x[i] = __float2half_rn(src[i]);
}
__global__ void split_w_kernel(const float* __restrict__ w0, const float* __restrict__ w1,
                               const float* __restrict__ w2, const float* __restrict__ w3) {
    int idx = blockIdx.y;
    const float* src = (idx == 0) ? w0 : (idx == 1) ? w1 : (idx == 2) ? w2 : w3;
    size_t off = (size_t)idx * 1048576;
    for (size_t i = (size_t)blockIdx.x * blockDim.x + threadIdx.x; i < 1048576;
         i += (size_t)gridDim.x * blockDim.x)
        g_w[off + i] = __float2half_rn(src[i]);
}

// ---------------- projection GEMM: 128m x 128n, fp16, 64-wide k-slabs ----------
// OPROJ=0: QKV via blockIdx.z (0:Q scaled, 1:K, 2:V) -> fp16 scratch
// OPROJ=1: O projection (ctx @ Wo^T + bias) -> fp32 out
// stage: A 128x64 (stride 144B, 18432) + B same = 36864B; 2 stages; 2 CTAs/SM
#define PST 36864

template<int OPROJ>
__global__ void __launch_bounds__(256, 2)
proj_kernel(const float* __restrict__ bias, float* __restrict__ out)
{
    extern __shared__ char smem[];
    const uint32_t sb = su32(smem);
    const int tid = threadIdx.x;
    const int lane = tid & 31, wid = tid >> 5;
    const int wm = wid >> 2, wn = wid & 3;
    const int g = lane >> 2, tig = lane & 3;
    const int m0 = blockIdx.x * 128, n0 = blockIdx.y * 128;
    const int mode = OPROJ ? 3 : (int)blockIdx.z;

    const __half* A = OPROJ ? g_c : g_x;
    const __half* B = g_w + (size_t)mode * 1048576;

    float acc[4][4][4];
#pragma unroll
    for (int i = 0; i < 4; i++)
#pragma unroll
        for (int j = 0; j < 4; j++)
#pragma unroll
            for (int e = 0; e < 4; e++) acc[i][j][e] = 0.0f;

    auto load_stage = [&](int kt, int buf) {
        uint32_t base = sb + buf * PST;
#pragma unroll
        for (int t = 0; t < 8; t++) {
            int vi = tid + t * 256;       // 0..2047
            int tile = vi >> 10;          // 0 A, 1 B
            int row = (vi >> 3) & 127;
            int ch = vi & 7;
            const __half* src = (tile ? B + (size_t)(n0 + row) * 1024
                                      : A + (size_t)(m0 + row) * 1024) + kt + ch * 8;
            cpa16(base + tile * 18432 + row * 144 + ch * 16, src);
        }
        CP_COMMIT();
    };

    load_stage(0, 0);
    for (int s = 0; s < 16; s++) {
        if (s < 15) { load_stage((s + 1) * 64, (s + 1) & 1); CP_WAIT1(); }
        else CP_WAIT0();
        __syncthreads();
        uint32_t base = sb + (s & 1) * PST;
#pragma unroll
        for (int ks = 0; ks < 4; ks++) {
            uint32_t af[4][4];
#pragma unroll
            for (int mf = 0; mf < 4; mf++) {
                uint32_t a = base + (uint32_t)(wm * 64 + mf * 16 + (lane & 15)) * 144
                           + (ks * 16 + (lane >> 4) * 8) * 2;
                ldsm4(af[mf], a);
            }
#pragma unroll
            for (int g2 = 0; g2 < 2; g2++) {
                uint32_t bf[4];
                uint32_t a = base + 18432
                           + (uint32_t)(wn * 32 + g2 * 16 + (lane & 7) + ((lane >> 4) << 3)) * 144
                           + (ks * 16 + ((lane >> 3) & 1) * 8) * 2;
                ldsm4(bf, a);
#pragma unroll
                for (int mf = 0; mf < 4; mf++)
#pragma unroll
                    for (int j = 0; j < 2; j++)
                        mma_f16(acc[mf][g2 * 2 + j], af[mf], &bf[j * 2]);
            }
        }
        __syncthreads();
    }

    // epilogue
    const float scale = (mode == 0) ? QSCALE : 1.0f;
#pragma unroll
    for (int mf = 0; mf < 4; mf++) {
#pragma unroll
        for (int half = 0; half < 2; half++) {
            int m = m0 + wm * 64 + mf * 16 + g + half * 8;
#pragma unroll
            for (int nf = 0; nf < 4; nf++) {
                int n = n0 + wn * 32 + nf * 8 + 2 * tig;
                float v0 = acc[mf][nf][half * 2] * scale;
                float v1 = acc[mf][nf][half * 2 + 1] * scale;
                if (OPROJ) {
                    float2 o = make_float2(v0 + bias[n], v1 + bias[n + 1]);
                    *(float2*)(out + (size_t)m * 1024 + n) = o;
                } else {
                    int b = m >> 11, ss = m & 2047;
                    int h = n >> 6, d = n & 63;
                    size_t addr = (((size_t)(b * 16 + h) * 2048) + ss) * 64 + d;
                    __half* D = (mode == 0) ? g_q : (mode == 1) ? g_k : g_v;
                    *(uint32_t*)(D + addr) = pack2h(v0, v1);
                }
            }
        }
    }
}

// ---------------- attention: fp16, 4 warps x 32 q-rows, double-buffered ----------
// 128 threads, 2 CTAs/SM. Q tile 128x64 (stride 144B). KV stage: K+V (18432 each).
// SMEM: Q 0; KV stage s at 18432+s*36864; bias at 92160+s*1024. Total 94208.
#define AT_TS  18432
#define AT_Q   0
#define AT_KV  18432
#define AT_KVS 36864
#define AT_SB  92160
#define AT_SMEM 94208

__global__ void __launch_bounds__(128, 2)
attn_kernel(const float* __restrict__ bias_table)
{
    extern __shared__ char smem[];
    const uint32_t sb = su32(smem);
    const int tid = threadIdx.x;
    const int lane = tid & 31, w = tid >> 5;    // 4 warps
    const int g = lane >> 2, tig = lane & 3;
    const int bh = blockIdx.y;
    const int b = bh >> 4, h = bh & 15;
    const int q0 = blockIdx.x * 128;

    // Q tile: 1024 x 16B chunks, 128 threads -> 8 iters
#pragma unroll
    for (int t2 = 0; t2 < 8; t2++) {
        int vi = tid + t2 * 128;
        int row = (vi >> 3) & 127;
        int ch = vi & 7;
        cpa16(sb + AT_Q + row * 144 + ch * 16,
              g_q + ((size_t)bh * 2048 + q0 + row) * 64 + ch * 8);
    }

    auto issue_kv = [&](int buf, int k0) {
        uint32_t base = sb + AT_KV + buf * AT_KVS;
#pragma unroll
        for (int u = 0; u < 16; u++) {
            int vi = tid + u * 128;
            int tile = vi >> 10;          // 0 K, 1 V
            int row = (vi >> 3) & 127;
            int ch = vi & 7;
            const __half* src = (tile ? g_v : g_k)
                + ((size_t)bh * 2048 + k0 + row) * 64 + ch * 8;
            cpa16(base + tile * AT_TS + row * 144 + ch * 16, src);
        }
        // bias window: 255 floats
        cpa4(sb + AT_SB + buf * 1024 + tid * 4,
             bias_table + (size_t)(q0 - k0 + 1920 + tid) * 16 + h);
        if (tid < 127)
            cpa4(sb + AT_SB + buf * 1024 + (tid + 128) * 4,
                 bias_table + (size_t)(q0 - k0 + 2048 + tid) * 16 + h);
    };

    issue_kv(0, 0);
    CP_COMMIT();   // group: Q + KV0

    float oacc[2][8][4];
#pragma unroll
    for (int mf = 0; mf < 2; mf++)
#pragma unroll
        for (int i = 0; i < 8; i++)
#pragma unroll
            for (int e = 0; e < 4; e++) oacc[mf][i][e] = 0.0f;
    float lsA[2] = {0.0f, 0.0f}, lsB[2] = {0.0f, 0.0f};

    const int d0[2] = { w * 32 + g - 2 * tig + 127,
                        w * 32 + 16 + g - 2 * tig + 127 };

    for (int t = 0; t < 16; t++) {
        if (t < 15) { issue_kv((t + 1) & 1, (t + 1) * 128); CP_COMMIT(); CP_WAIT1(); }
        else CP_WAIT0();
        __syncthreads();

        const uint32_t kvb = sb + AT_KV + (t & 1) * AT_KVS;
        const float* sbias = (const float*)(smem + AT_SB + (t & 1) * 1024);

#pragma unroll
        for (int half = 0; half < 2; half++) {
            // ---- S(half) = Q @ K[half]^T (log2-scaled), 2 m-frags x 64 cols ----
            float sacc[2][8][4];
#pragma unroll
            for (int mf = 0; mf < 2; mf++)
#pragma unroll
                for (int i = 0; i < 8; i++)
#pragma unroll
                    for (int e = 0; e < 4; e++) sacc[mf][i][e] = 0.0f;
#pragma unroll
            for (int ks = 0; ks < 4; ks++) {
                uint32_t qf[2][4];
#pragma unroll
                for (int mf = 0; mf < 2; mf++) {
                    uint32_t a = sb + AT_Q
                        + (uint32_t)(w * 32 + mf * 16 + (lane & 15)) * 144
                        + (ks * 16 + (lane >> 4) * 8) * 2;
                    ldsm4(qf[mf], a);
                }
                uint32_t kf[4][4];
#pragma unroll
                for (int g2 = 0; g2 < 4; g2++) {
                    uint32_t a = kvb
                        + (uint32_t)(half * 64 + g2 * 16 + (lane & 7) + ((lane >> 4) << 3)) * 144
                        + (ks * 16 + ((lane >> 3) & 1) * 8) * 2;
                    ldsm4(kf[g2], a);
                }
#pragma unroll
                for (int mf = 0; mf < 2; mf++)
#pragma unroll
                    for (int nf2 = 0; nf2 < 8; nf2++)
                        mma_f16(sacc[mf][nf2], qf[mf], &kf[nf2 >> 1][(nf2 & 1) * 2]);
            }

            // ---- P(half) = 2^(S + bias*log2e): C-frag -> A-frag, fp16 ----
            uint32_t pf[2][4][4];
#pragma unroll
            for (int mf = 0; mf < 2; mf++) {
#pragma unroll
                for (int ks2 = 0; ks2 < 4; ks2++) {
#pragma unroll
                    for (int j = 0; j < 2; j++) {
                        int nf2 = 2 * ks2 + j;
                        float* c = sacc[mf][nf2];
                        int idx = d0[mf] - (half * 8 + nf2) * 8;
                        float p0 = ex2f(fmaf(sbias[idx],     LOG2E, c[0]));
                        float p1 = ex2f(fmaf(sbias[idx - 1], LOG2E, c[1]));
                        float p2 = ex2f(fmaf(sbias[idx + 8], LOG2E, c[2]));
                        float p3 = ex2f(fmaf(sbias[idx + 7], LOG2E, c[3]));
                        lsA[mf] += p0 + p1;
                        lsB[mf] += p2 + p3;
                        pf[mf][ks2][j * 2 + 0] = pack2h(p0, p1);
                        pf[mf][ks2][j * 2 + 1] = pack2h(p2, p3);
                    }
                }
            }

            // ---- O += P(half) @ V[half] ----
            const uint32_t vb = kvb + AT_TS;
#pragma unroll
            for (int ks2 = 0; ks2 < 4; ks2++) {
                uint32_t vf[4][4];
#pragma unroll
                for (int dblk = 0; dblk < 4; dblk++) {
                    uint32_t a = vb
                        + (uint32_t)(half * 64 + ks2 * 16 + (lane & 7) + ((lane >> 3) & 1) * 8) * 144
                        + (dblk * 16 + ((lane >> 4) << 3)) * 2;
                    ldsm4t(vf[dblk], a);
                }
#pragma unroll
                for (int mf = 0; mf < 2; mf++)
#pragma unroll
                    for (int dblk = 0; dblk < 4; dblk++)
#pragma unroll
                        for (int sub = 0; sub < 2; sub++)
                            mma_f16(oacc[mf][dblk * 2 + sub], pf[mf][ks2], &vf[dblk][sub * 2]);
            }
        }
        __syncthreads();
    }

    // ---- row-sum reduce within quad, epilogue (per m-frag) ----
#pragma unroll
    for (int mf = 0; mf < 2; mf++) {
        lsA[mf] += __shfl_xor_sync(0xffffffffu, lsA[mf], 1);
        lsA[mf] += __shfl_xor_sync(0xffffffffu, lsA[mf], 2);
        lsB[mf] += __shfl_xor_sync(0xffffffffu, lsB[mf], 1);
        lsB[mf] += __shfl_xor_sync(0xffffffffu, lsB[mf], 2);
        const float inv0 = 1.0f / lsA[mf];
        const float inv1 = 1.0f / lsB[mf];
        const int row0 = q0 + w * 32 + mf * 16 + g;
        const size_t base0 = (size_t)(b * 2048 + row0) * 1024 + h * 64;
        const size_t base1 = (size_t)(b * 2048 + row0 + 8) * 1024 + h * 64;
#pragma unroll
        for (int nfd = 0; nfd < 8; nfd++) {
            int d = nfd * 8 + 2 * tig;
            *(uint32_t*)(g_c + base0 + d) = pack2h(oacc[mf][nfd][0] * inv0, oacc[mf][nfd][1] * inv0);
            *(uint32_t*)(g_c + base1 + d) = pack2h(oacc[mf][nfd][2] * inv1, oacc[mf][nfd][3] * inv1);
        }
    }
}

// ---------------- launch ----------------
extern "C" void kernel_launch(void* const* d_in, const int* in_sizes, int n_in,
                              void* d_out, int out_size)
{
    const float* x  = (const float*)d_in[0];
    const float* Wq = (const float*)d_in[1];
    const float* Wk = (const float*)d_in[2];
    const float* Wv = (const float*)d_in[3];
    const float* Wo = (const float*)d_in[4];
    const float* bo = (const float*)d_in[5];
    const float* bt = (const float*)d_in[6];
    float* out = (float*)d_out;

    cudaFuncSetAttribute(proj_kernel<0>, cudaFuncAttributeMaxDynamicSharedMemorySize, 2 * PST);
    cudaFuncSetAttribute(proj_kernel<1>, cudaFuncAttributeMaxDynamicSharedMemorySize, 2 * PST);
    cudaFuncSetAttribute(attn_kernel,    cudaFuncAttributeMaxDynamicSharedMemorySize, AT_SMEM);

    split_x_kernel<<<2048, 256>>>(x);
    split_w_kernel<<<dim3(256, 4), 256>>>(Wq, Wk, Wv, Wo);

    proj_kernel<0><<<dim3(64, 8, 3), 256, 2 * PST>>>(nullptr, nullptr);

    attn_kernel<<<dim3(16, 64), 128, AT_SMEM>>>(bt);

    proj_kernel<1><<<dim3(64, 8), 256, 2 * PST>>>(bo, out);
}